// round 17
// baseline (speedup 1.0000x reference)
#include <cuda_runtime.h>
#include <cuda_bf16.h>
#include <cstdint>
#include <cstddef>

// Problem constants
#define Bb   8
#define Ll   1024
#define Dd   512
#define Hh   8
#define Qd   64
#define Mrows (Bb*Ll)          // 8192

// ---------------------------------------------------------------------------
// Scratch (no cudaMalloc allowed)
// ---------------------------------------------------------------------------
__device__ __nv_bfloat16 g_xhi [Mrows*Dd];
__device__ __nv_bfloat16 g_xlo [Mrows*Dd];
__device__ __nv_bfloat16 g_xrhi[Mrows*Dd];
__device__ __nv_bfloat16 g_xrlo[Mrows*Dd];
__device__ __nv_bfloat16 g_Qhi [Mrows*Dd];
__device__ __nv_bfloat16 g_Qlo [Mrows*Dd];
__device__ __nv_bfloat16 g_Khi [Mrows*Dd];
__device__ __nv_bfloat16 g_Klo [Mrows*Dd];
__device__ __nv_bfloat16 g_Vthi[Mrows*Dd];  // Vt[(b*512 + h*64 + d)*1024 + l]
__device__ __nv_bfloat16 g_Vtlo[Mrows*Dd];
__device__ __nv_bfloat16 g_mghi[Mrows*Dd];  // merged[b,l, d*H + h]
__device__ __nv_bfloat16 g_mglo[Mrows*Dd];
__device__ __nv_bfloat16 g_whi [5*Dd*Dd];   // Wc,Wq,Wk,Wv,Wo
__device__ __nv_bfloat16 g_wlo [5*Dd*Dd];

// ---------------------------------------------------------------------------
// PTX helpers
// ---------------------------------------------------------------------------
__device__ __forceinline__ uint32_t smem_u32(const void* p) {
    uint32_t a;
    asm("{ .reg .u64 t; cvta.to.shared.u64 t, %1; cvt.u32.u64 %0, t; }" : "=r"(a) : "l"(p));
    return a;
}
__device__ __forceinline__ void ldsm_x4(uint32_t* r, uint32_t addr) {
    asm volatile("ldmatrix.sync.aligned.m8n8.x4.shared.b16 {%0,%1,%2,%3}, [%4];"
        : "=r"(r[0]), "=r"(r[1]), "=r"(r[2]), "=r"(r[3]) : "r"(addr));
}
__device__ __forceinline__ void ldsm_x2(uint32_t* r, uint32_t addr) {
    asm volatile("ldmatrix.sync.aligned.m8n8.x2.shared.b16 {%0,%1}, [%2];"
        : "=r"(r[0]), "=r"(r[1]) : "r"(addr));
}
__device__ __forceinline__ void mma16816(float* c, const uint32_t* a, const uint32_t* b) {
    asm volatile("mma.sync.aligned.m16n8k16.row.col.f32.bf16.bf16.f32 "
        "{%0,%1,%2,%3}, {%4,%5,%6,%7}, {%8,%9}, {%0,%1,%2,%3};"
        : "+f"(c[0]), "+f"(c[1]), "+f"(c[2]), "+f"(c[3])
        : "r"(a[0]), "r"(a[1]), "r"(a[2]), "r"(a[3]), "r"(b[0]), "r"(b[1]));
}
__device__ __forceinline__ void cp_async16(uint32_t s, const void* g) {
    asm volatile("cp.async.cg.shared.global [%0], [%1], 16;" :: "r"(s), "l"(g));
}
__device__ __forceinline__ void cp_commit() { asm volatile("cp.async.commit_group;" ::: "memory"); }
__device__ __forceinline__ void cp_wait0()  { asm volatile("cp.async.wait_group 0;" ::: "memory"); }

// ---------------------------------------------------------------------------
// fp32 -> bf16 hi/lo split helpers
// ---------------------------------------------------------------------------
__device__ __forceinline__ void split_store(float vx, float vy,
                                            __nv_bfloat16* hi, __nv_bfloat16* lo, size_t idx)
{
    __nv_bfloat162 ph, pl;
    ph.x = __float2bfloat16(vx); ph.y = __float2bfloat16(vy);
    pl.x = __float2bfloat16(vx - __bfloat162float(ph.x));
    pl.y = __float2bfloat16(vy - __bfloat162float(ph.y));
    *reinterpret_cast<__nv_bfloat162*>(hi + idx) = ph;
    *reinterpret_cast<__nv_bfloat162*>(lo + idx) = pl;
}

__global__ void cvt_split(const float* __restrict__ in,
                          __nv_bfloat16* __restrict__ hi,
                          __nv_bfloat16* __restrict__ lo, int n4)
{
    int i = blockIdx.x * blockDim.x + threadIdx.x;
    if (i >= n4) return;
    float4 v = reinterpret_cast<const float4*>(in)[i];
    split_store(v.x, v.y, hi, lo, (size_t)i * 4);
    split_store(v.z, v.w, hi, lo, (size_t)i * 4 + 2);
}

__global__ void cvt_split5(const float* __restrict__ w0, const float* __restrict__ w1,
                           const float* __restrict__ w2, const float* __restrict__ w3,
                           const float* __restrict__ w4,
                           __nv_bfloat16* __restrict__ hi, __nv_bfloat16* __restrict__ lo)
{
    const int seg = blockIdx.y;
    const float* in = (seg == 0) ? w0 : (seg == 1) ? w1 : (seg == 2) ? w2 : (seg == 3) ? w3 : w4;
    hi += (size_t)seg * Dd * Dd;
    lo += (size_t)seg * Dd * Dd;
    int i = blockIdx.x * blockDim.x + threadIdx.x;
    float4 v = reinterpret_cast<const float4*>(in)[i];
    split_store(v.x, v.y, hi, lo, (size_t)i * 4);
    split_store(v.z, v.w, hi, lo, (size_t)i * 4 + 2);
}

// ---------------------------------------------------------------------------
// HMMA split-precision GEMM, cp.async double-buffered (1 sync per chunk).
// ---------------------------------------------------------------------------
#define LDTB 80
#define GSTG 40960
#define GM_SMEM (2*GSTG)

__global__ __launch_bounds__(256, 2)
void tg_gemm(const __nv_bfloat16* __restrict__ Ahi, const __nv_bfloat16* __restrict__ Alo,
             const __nv_bfloat16* __restrict__ Whi, const __nv_bfloat16* __restrict__ Wlo,
             const float* __restrict__ bias, float* __restrict__ C,
             __nv_bfloat16* __restrict__ Chi, __nv_bfloat16* __restrict__ Clo,
             int mode)
{
    extern __shared__ char gsm[];
    const uint32_t sb0 = smem_u32(gsm);

    const int tid  = threadIdx.x;
    const int wid  = tid >> 5;
    const int lane = tid & 31;
    const int bm   = blockIdx.x * 128;
    const int bn   = blockIdx.y * 128;
    const int wm = (wid >> 2) * 64;
    const int wn = (wid & 3) * 32;

    float acc[4][4][4];
#pragma unroll
    for (int i = 0; i < 4; i++)
#pragma unroll
        for (int j = 0; j < 4; j++)
#pragma unroll
            for (int k = 0; k < 4; k++) acc[i][j][k] = 0.0f;

    const int a_row  = wm + (lane & 15);
    const int a_colb = (lane >> 4) * 16;
    const int b_row  = wn + ((lane >> 4) << 3) + (lane & 7);
    const int b_colb = ((lane >> 3) & 1) * 16;

    const int l_row0 = tid >> 1;
    const int l_c0   = (tid & 1) * 2;

#define GM_LOAD(cch, stg) do {                                                  \
        uint32_t _sb = sb0 + (stg) * GSTG;                                      \
        _Pragma("unroll")                                                       \
        for (int cc = 0; cc < 2; cc++) {                                        \
            int c16 = l_c0 + cc;                                                \
            size_t ga = (size_t)(bm + l_row0) * 512 + (cch) * 32 + c16 * 8;     \
            size_t gw = (size_t)(bn + l_row0) * 512 + (cch) * 32 + c16 * 8;     \
            uint32_t so = (uint32_t)(l_row0 * LDTB + c16 * 16);                 \
            cp_async16(_sb + so,         Ahi + ga);                             \
            cp_async16(_sb + 10240 + so, Alo + ga);                             \
            cp_async16(_sb + 20480 + so, Whi + gw);                             \
            cp_async16(_sb + 30720 + so, Wlo + gw);                             \
        }                                                                       \
    } while (0)

    GM_LOAD(0, 0); cp_commit();

    for (int c = 0; c < 16; c++) {
        cp_wait0();
        __syncthreads();
        if (c < 15) { GM_LOAD(c + 1, (c + 1) & 1); cp_commit(); }

        const uint32_t ua  = sb0 + (c & 1) * GSTG;
        const uint32_t ual = ua + 10240;
        const uint32_t uwh = ua + 20480;
        const uint32_t uwl = ua + 30720;

#pragma unroll
        for (int ks = 0; ks < 2; ks++) {
            const int kb = ks * 32;
            uint32_t af[4][4];
            uint32_t bh[2][4], bl[2][4];
#pragma unroll
            for (int mf = 0; mf < 4; mf++)
                ldsm_x4(af[mf], ua + (uint32_t)((a_row + mf * 16) * LDTB) + kb + a_colb);
#pragma unroll
            for (int p = 0; p < 2; p++) {
                uint32_t off = (uint32_t)((b_row + p * 16) * LDTB) + kb + b_colb;
                ldsm_x4(bh[p], uwh + off);
                ldsm_x4(bl[p], uwl + off);
            }
#pragma unroll
            for (int mf = 0; mf < 4; mf++)
#pragma unroll
                for (int nf = 0; nf < 4; nf++) {
                    mma16816(acc[mf][nf], af[mf], &bh[nf >> 1][(nf & 1) * 2]);
                    mma16816(acc[mf][nf], af[mf], &bl[nf >> 1][(nf & 1) * 2]);
                }
#pragma unroll
            for (int mf = 0; mf < 4; mf++)
                ldsm_x4(af[mf], ual + (uint32_t)((a_row + mf * 16) * LDTB) + kb + a_colb);
#pragma unroll
            for (int mf = 0; mf < 4; mf++)
#pragma unroll
                for (int nf = 0; nf < 4; nf++)
                    mma16816(acc[mf][nf], af[mf], &bh[nf >> 1][(nf & 1) * 2]);
        }
    }

    // ---- epilogue ----
    const int gid = lane >> 2;
    const int tq  = lane & 3;
#pragma unroll
    for (int mf = 0; mf < 4; mf++) {
#pragma unroll
        for (int nf = 0; nf < 4; nf++) {
            const float* a = acc[mf][nf];
            int m0 = bm + wm + mf * 16 + gid;
            int n0 = bn + wn + nf * 8 + tq * 2;
            float b0 = __ldg(&bias[n0]);
            float b1 = __ldg(&bias[n0 + 1]);
            float v0 = a[0] + b0, v1 = a[1] + b1;
            float v2 = a[2] + b0, v3 = a[3] + b1;
            if (mode == 0) {
                *reinterpret_cast<float2*>(&C[(size_t)m0 * 512 + n0])       = make_float2(v0, v1);
                *reinterpret_cast<float2*>(&C[(size_t)(m0 + 8) * 512 + n0]) = make_float2(v2, v3);
            } else if (mode == 2) {
                split_store(v0, v1, Chi, Clo, (size_t)m0 * 512 + n0);
                split_store(v2, v3, Chi, Clo, (size_t)(m0 + 8) * 512 + n0);
            } else {
                int bi0 = m0 >> 10, l0v = m0 & 1023;
                int m1 = m0 + 8;
                int bi1 = m1 >> 10, l1v = m1 & 1023;
                __nv_bfloat16 h;
                h = __float2bfloat16(v0);
                Chi[((size_t)(bi0*512 + n0    ))*1024 + l0v] = h;
                Clo[((size_t)(bi0*512 + n0    ))*1024 + l0v] = __float2bfloat16(v0 - __bfloat162float(h));
                h = __float2bfloat16(v1);
                Chi[((size_t)(bi0*512 + n0 + 1))*1024 + l0v] = h;
                Clo[((size_t)(bi0*512 + n0 + 1))*1024 + l0v] = __float2bfloat16(v1 - __bfloat162float(h));
                h = __float2bfloat16(v2);
                Chi[((size_t)(bi1*512 + n0    ))*1024 + l1v] = h;
                Clo[((size_t)(bi1*512 + n0    ))*1024 + l1v] = __float2bfloat16(v2 - __bfloat162float(h));
                h = __float2bfloat16(v3);
                Chi[((size_t)(bi1*512 + n0 + 1))*1024 + l1v] = h;
                Clo[((size_t)(bi1*512 + n0 + 1))*1024 + l1v] = __float2bfloat16(v3 - __bfloat162float(h));
            }
        }
    }
}

// ---------------------------------------------------------------------------
// Fused attention v2: 16-row Q tiles, 64-token K/V chunks, 2 CTAs/SM.
// HMMA split QK^T and PV; P converted once per chunk into smem.
// ---------------------------------------------------------------------------
#define SROW 1028
#define AOFF_QHI  65792                        // 16*1028*4
#define AOFF_QLO  (AOFF_QHI + 2304)            // 16*72*2
#define AOFF_PHI  (AOFF_QLO + 2304)            // 70400
#define AOFF_PLO  (AOFF_PHI + 2304)            // 72704
#define AOFF_K    (AOFF_PLO + 2304)            // 75008
#define KSTG      18432                        // (Kh 9216 + Kl 9216), V aliases
#define ATTN_SMEM_BYTES (AOFF_K + 2*KSTG)      // 111872

__global__ __launch_bounds__(256, 2)
void attn_mma(const __nv_bfloat16* __restrict__ Qhi, const __nv_bfloat16* __restrict__ Qlo,
              const __nv_bfloat16* __restrict__ Khi, const __nv_bfloat16* __restrict__ Klo,
              const __nv_bfloat16* __restrict__ Vthi, const __nv_bfloat16* __restrict__ Vtlo,
              float* __restrict__ scores,
              __nv_bfloat16* __restrict__ mghi, __nv_bfloat16* __restrict__ mglo)
{
    extern __shared__ char smc[];
    float* S = reinterpret_cast<float*>(smc);
    __nv_bfloat16* sQh = reinterpret_cast<__nv_bfloat16*>(smc + AOFF_QHI);
    __nv_bfloat16* sQl = reinterpret_cast<__nv_bfloat16*>(smc + AOFF_QLO);
    __nv_bfloat16* sPh = reinterpret_cast<__nv_bfloat16*>(smc + AOFF_PHI);
    __nv_bfloat16* sPl = reinterpret_cast<__nv_bfloat16*>(smc + AOFF_PLO);

    const uint32_t ub  = smem_u32(smc);
    const uint32_t uQh = ub + AOFF_QHI, uQl = ub + AOFF_QLO;
    const uint32_t uPh = ub + AOFF_PHI, uPl = ub + AOFF_PLO;
    const uint32_t uK  = ub + AOFF_K;

    const int tid  = threadIdx.x;
    const int lane = tid & 31;
    const int w    = tid >> 5;
    const int qt   = blockIdx.x;     // 0..63
    const int h    = blockIdx.y;
    const int b    = blockIdx.z;
    const int l0   = qt * 16;

    // K chunk: 64 tokens x 64 dims, hi+lo, row stride 144B
#define K_LOAD(jt, stg) do {                                                        \
        uint32_t _kb = uK + (stg) * KSTG;                                           \
        _Pragma("unroll")                                                           \
        for (int i = 0; i < 2; i++) {                                               \
            int idx = tid + i * 256;                                                \
            int r = idx >> 3, c8 = idx & 7;                                         \
            size_t g = ((size_t)(b * 1024 + (jt) * 64 + r)) * 512 + h * 64 + c8 * 8; \
            uint32_t so = (uint32_t)(r * 144 + c8 * 16);                            \
            cp_async16(_kb + so,        Khi + g);                                   \
            cp_async16(_kb + 9216 + so, Klo + g);                                   \
        }                                                                           \
    } while (0)

    // V chunk: 64 dims x 64 tokens, hi+lo, row stride 144B (aliases K region)
#define V_LOAD(jt, stg) do {                                                        \
        uint32_t _vb = uK + (stg) * KSTG;                                           \
        _Pragma("unroll")                                                           \
        for (int i = 0; i < 2; i++) {                                               \
            int idx = tid + i * 256;                                                \
            int r = idx >> 3, c = idx & 7;                                          \
            size_t g = ((size_t)(b * 512 + h * 64 + r)) * 1024 + (jt) * 64 + c * 8; \
            uint32_t so = (uint32_t)(r * 144 + c * 16);                             \
            cp_async16(_vb + so,        Vthi + g);                                  \
            cp_async16(_vb + 9216 + so, Vtlo + g);                                  \
        }                                                                           \
    } while (0)

    // prefetch K0 while loading Q
    K_LOAD(0, 0); cp_commit();

    if (tid < 128) {
        int r = tid >> 3, c = tid & 7;
        size_t g = ((size_t)(b * 1024 + l0 + r)) * 512 + h * 64 + c * 8;
        *reinterpret_cast<uint4*>(&sQh[r * 72 + c * 8]) = *reinterpret_cast<const uint4*>(&Qhi[g]);
        *reinterpret_cast<uint4*>(&sQl[r * 72 + c * 8]) = *reinterpret_cast<const uint4*>(&Qlo[g]);
    }
    __syncthreads();

    const int a_row  = lane & 15;
    const int a_colb = (lane >> 4) * 16;
    const int gid = lane >> 2;
    const int tq  = lane & 3;

    // hoist Q fragments (16 rows -> mf=1)
    uint32_t qh[4][4], ql[4][4];
#pragma unroll
    for (int kk = 0; kk < 4; kk++) {
        uint32_t off = (uint32_t)(a_row * 144) + kk * 32 + a_colb;
        ldsm_x4(qh[kk], uQh + off);
        ldsm_x4(ql[kk], uQl + off);
    }

    // ---- S phase: 16 chunks of 64 tokens; warp owns 8 cols per chunk ----
    {
        const int wn = w * 8;
        const int b_row  = wn + (lane & 7);
        const int b_colb = ((lane >> 3) & 1) * 16;
        for (int jt = 0; jt < 16; jt++) {
            cp_wait0();
            __syncthreads();
            if (jt < 15) { K_LOAD(jt + 1, (jt + 1) & 1); cp_commit(); }
            const uint32_t uKh = uK + (jt & 1) * KSTG;
            const uint32_t uKl = uKh + 9216;

            float acc[4];
#pragma unroll
            for (int k = 0; k < 4; k++) acc[k] = 0.0f;

#pragma unroll
            for (int kk = 0; kk < 4; kk++) {
                uint32_t bhf[2], blf[2];
                uint32_t off = (uint32_t)(b_row * 144) + kk * 32 + b_colb;
                ldsm_x2(bhf, uKh + off);
                ldsm_x2(blf, uKl + off);
                mma16816(acc, qh[kk], bhf);
                mma16816(acc, qh[kk], blf);
                mma16816(acc, ql[kk], bhf);
            }
            int col = jt * 64 + wn + tq * 2;
            *reinterpret_cast<float2*>(&S[(size_t)gid * SROW + col]) =
                make_float2(acc[0] * 0.125f, acc[1] * 0.125f);
            *reinterpret_cast<float2*>(&S[(size_t)(gid + 8) * SROW + col]) =
                make_float2(acc[2] * 0.125f, acc[3] * 0.125f);
        }
    }

    // prefetch V0 (stage0; chunk15 readers use stage1) — overlaps softmax
    V_LOAD(0, 0); cp_commit();
    __syncthreads();   // S complete

    // ---- softmax: warp owns 2 rows; write scores once ----
    {
        for (int rr = 0; rr < 2; rr++) {
            int r = w * 2 + rr;
            float* row = &S[(size_t)r * SROW];
            float mx = -1e30f;
            for (int j = lane; j < 1024; j += 32) mx = fmaxf(mx, row[j]);
#pragma unroll
            for (int o = 16; o; o >>= 1) mx = fmaxf(mx, __shfl_xor_sync(0xffffffffu, mx, o));
            float s = 0.0f;
            for (int j = lane; j < 1024; j += 32) {
                float e = __expf(row[j] - mx);
                row[j] = e;
                s += e;
            }
#pragma unroll
            for (int o = 16; o; o >>= 1) s += __shfl_xor_sync(0xffffffffu, s, o);
            float inv = 1.0f / s;
            float* sg = scores + (((size_t)(b * 8 + h)) * 1024 + (l0 + r)) * 1024;
            for (int j = lane; j < 1024; j += 32) {
                float p = row[j] * inv;
                row[j] = p;
                sg[j]  = p;
            }
        }
    }
    __syncthreads();

    // ---- PV phase: 16 chunks; P converted once per chunk into smem ----
    {
        const int d0 = w * 8;           // warp dims
        float acc[4];
#pragma unroll
        for (int k = 0; k < 4; k++) acc[k] = 0.0f;

        const int v_rowb = (d0 + (lane & 7)) * 144;
        const int v_selb = (lane >> 3) * 16;          // token tile select (4 tiles)

        for (int jt = 0; jt < 16; jt++) {
            cp_wait0();
            __syncthreads();            // prev chunk MMAs/P reads done
            if (jt < 15) { V_LOAD(jt + 1, (jt + 1) & 1); cp_commit(); }

            // convert P chunk 16x64 -> sPh/sPl (stride 72 bf16); 2 float2/thread
#pragma unroll
            for (int i = 0; i < 2; i++) {
                int idx = tid + i * 256;              // 0..511
                int r = idx >> 5, c2 = (idx & 31) * 2;
                float2 v = *reinterpret_cast<const float2*>(&S[(size_t)r * SROW + jt * 64 + c2]);
                __nv_bfloat162 ph, pl;
                ph.x = __float2bfloat16(v.x);
                ph.y = __float2bfloat16(v.y);
                pl.x = __float2bfloat16(v.x - __bfloat162float(ph.x));
                pl.y = __float2bfloat16(v.y - __bfloat162float(ph.y));
                *reinterpret_cast<__nv_bfloat162*>(&sPh[r * 72 + c2]) = ph;
                *reinterpret_cast<__nv_bfloat162*>(&sPl[r * 72 + c2]) = pl;
            }
            __syncthreads();            // P visible

            const uint32_t uVh = uK + (jt & 1) * KSTG;
            const uint32_t uVl = uVh + 9216;

            // V fragments: 2 ldsm_x4 per component cover all 64 tokens
            uint32_t vh[2][4], vl[2][4];
#pragma unroll
            for (int kp = 0; kp < 2; kp++) {
                uint32_t voff = (uint32_t)(v_rowb + kp * 64 + v_selb);
                ldsm_x4(vh[kp], uVh + voff);
                ldsm_x4(vl[kp], uVl + voff);
            }
            // P fragments + MMA: kk = kp*2 + k2
#pragma unroll
            for (int kk = 0; kk < 4; kk++) {
                uint32_t ah[4], al[4];
                uint32_t aoff = (uint32_t)(a_row * 144) + kk * 32 + a_colb;
                ldsm_x4(ah, uPh + aoff);
                ldsm_x4(al, uPl + aoff);
                const uint32_t* bh2 = &vh[kk >> 1][(kk & 1) * 2];
                const uint32_t* bl2 = &vl[kk >> 1][(kk & 1) * 2];
                mma16816(acc, ah, bh2);
                mma16816(acc, ah, bl2);
                mma16816(acc, al, bh2);
            }
        }

        // epilogue: merged[b, l, d*H + h] as split bf16
        {
            int row = l0 + gid;
            int d   = d0 + tq * 2;
            size_t base0 = ((size_t)(b * 1024 + row)) * 512 + h;
            size_t base1 = ((size_t)(b * 1024 + row + 8)) * 512 + h;
            __nv_bfloat16 hh;
            hh = __float2bfloat16(acc[0]);
            mghi[base0 + (size_t)d * 8]       = hh;
            mglo[base0 + (size_t)d * 8]       = __float2bfloat16(acc[0] - __bfloat162float(hh));
            hh = __float2bfloat16(acc[1]);
            mghi[base0 + (size_t)(d + 1) * 8] = hh;
            mglo[base0 + (size_t)(d + 1) * 8] = __float2bfloat16(acc[1] - __bfloat162float(hh));
            hh = __float2bfloat16(acc[2]);
            mghi[base1 + (size_t)d * 8]       = hh;
            mglo[base1 + (size_t)d * 8]       = __float2bfloat16(acc[2] - __bfloat162float(hh));
            hh = __float2bfloat16(acc[3]);
            mghi[base1 + (size_t)(d + 1) * 8] = hh;
            mglo[base1 + (size_t)(d + 1) * 8] = __float2bfloat16(acc[3] - __bfloat162float(hh));
        }
    }
}

// ---------------------------------------------------------------------------
// Launch
// ---------------------------------------------------------------------------
extern "C" void kernel_launch(void* const* d_in, const int* in_sizes, int n_in,
                              void* d_out, int out_size)
{
    const float* x  = (const float*)d_in[0];
    const float* Wc = (const float*)d_in[1];
    const float* bc = (const float*)d_in[2];
    const float* Wq = (const float*)d_in[3];
    const float* bq = (const float*)d_in[4];
    const float* Wk = (const float*)d_in[5];
    const float* bk = (const float*)d_in[6];
    const float* Wv = (const float*)d_in[7];
    const float* bv = (const float*)d_in[8];
    const float* Wo = (const float*)d_in[9];
    const float* bo = (const float*)d_in[10];

    float* out    = (float*)d_out;
    float* scores = out + (size_t)Bb * Ll * Dd;

    __nv_bfloat16 *xhi, *xlo, *xrhi, *xrlo, *qhi, *qlo, *khi, *klo,
                  *vthi, *vtlo, *mghi, *mglo, *whi, *wlo;
    cudaGetSymbolAddress((void**)&xhi,  g_xhi);
    cudaGetSymbolAddress((void**)&xlo,  g_xlo);
    cudaGetSymbolAddress((void**)&xrhi, g_xrhi);
    cudaGetSymbolAddress((void**)&xrlo, g_xrlo);
    cudaGetSymbolAddress((void**)&qhi,  g_Qhi);
    cudaGetSymbolAddress((void**)&qlo,  g_Qlo);
    cudaGetSymbolAddress((void**)&khi,  g_Khi);
    cudaGetSymbolAddress((void**)&klo,  g_Klo);
    cudaGetSymbolAddress((void**)&vthi, g_Vthi);
    cudaGetSymbolAddress((void**)&vtlo, g_Vtlo);
    cudaGetSymbolAddress((void**)&mghi, g_mghi);
    cudaGetSymbolAddress((void**)&mglo, g_mglo);
    cudaGetSymbolAddress((void**)&whi,  g_whi);
    cudaGetSymbolAddress((void**)&wlo,  g_wlo);

    cudaFuncSetAttribute((const void*)attn_mma,
                         cudaFuncAttributeMaxDynamicSharedMemorySize, ATTN_SMEM_BYTES);
    cudaFuncSetAttribute((const void*)tg_gemm,
                         cudaFuncAttributeMaxDynamicSharedMemorySize, GM_SMEM);

    const int WN = Dd * Dd;
    cvt_split<<<(Mrows*Dd/4 + 255)/256, 256>>>(x, xhi, xlo, Mrows*Dd/4);
    cvt_split5<<<dim3(WN/4/256, 5), 256>>>(Wc, Wq, Wk, Wv, Wo, whi, wlo);

    dim3 gg(Mrows / 128, Dd / 128);   // (64, 4)

    tg_gemm<<<gg, 256, GM_SMEM>>>(xhi, xlo, whi + 0*WN, wlo + 0*WN, bc,
                                  nullptr, xrhi, xrlo, 2);
    tg_gemm<<<gg, 256, GM_SMEM>>>(xhi, xlo, whi + 1*WN, wlo + 1*WN, bq,
                                  nullptr, qhi, qlo, 2);
    tg_gemm<<<gg, 256, GM_SMEM>>>(xrhi, xrlo, whi + 2*WN, wlo + 2*WN, bk,
                                  nullptr, khi, klo, 2);
    tg_gemm<<<gg, 256, GM_SMEM>>>(xrhi, xrlo, whi + 3*WN, wlo + 3*WN, bv,
                                  nullptr, vthi, vtlo, 3);

    attn_mma<<<dim3(64, Hh, Bb), 256, ATTN_SMEM_BYTES>>>(
        qhi, qlo, khi, klo, vthi, vtlo, scores, mghi, mglo);

    tg_gemm<<<gg, 256, GM_SMEM>>>(mghi, mglo, whi + 4*WN, wlo + 4*WN, bo,
                                  out, nullptr, nullptr, 0);
}